// round 10
// baseline (speedup 1.0000x reference)
#include <cuda_runtime.h>
#include <cstdint>

#define BB 512
#define TT 1024
#define CC 256
#define LL 64
#define SS 129          // 2*LL+1
#define SPL 5           // states per lane (32*5 = 160 >= 129, padded)
#define WROWS 8         // rows per memory window
#define NW (TT / WROWS) // 128 windows
#define RING 4          // ring depth in windows (32 KB SMEM)
#define PREF 3          // prefetch distance (windows)
#define EPSF 1e-7f
#define LN2F 0.69314718055994530942f
#define FULLM 0xffffffffu

__device__ __forceinline__ void cpa16(uint32_t dst, const float* src) {
    asm volatile("cp.async.cg.shared.global [%0], [%1], 16;" :: "r"(dst), "l"(src) : "memory");
}
__device__ __forceinline__ void cpcommit() {
    asm volatile("cp.async.commit_group;" ::: "memory");
}
__device__ __forceinline__ void cpwait2() {
    asm volatile("cp.async.wait_group 2;" ::: "memory");
}

__global__ void __launch_bounds__(64)
ctc_warp_kernel(const int* __restrict__ y_true,
                const float* __restrict__ y_pred,
                float* __restrict__ out)
{
    __shared__ float ring[RING * WROWS * CC];   // 32 KB (rows padded to 256 floats)

    const int b     = blockIdx.x;
    const int tid   = threadIdx.x;
    const int lane  = tid & 31;
    const int wrp   = tid >> 5;
    const int blank = CC - 1;

    // ---- per-batch sector mask: which 32B sectors (8 classes) are ever read ----
    // Built identically (and redundantly) in both warps.
    const int* lbl = y_true + b * LL;
    uint32_t msk = 1u << 31;                    // blank (class 255) sector always needed
    {
        int c0 = lbl[2 * lane];
        int c1 = lbl[2 * lane + 1];
        msk |= (1u << (c0 >> 3)) | (1u << (c1 >> 3));
        msk = __reduce_or_sync(FULLM, msk);
    }
    const int nsec = __popc(msk);

    if (wrp == 1) {
        // ============ producer warp: loads ONLY needed sectors ============
        // Lane i (i < nsec) owns the i-th set sector; 32B per row = 2 cp.async.
        int sector = 0, cnt = 0;
#pragma unroll
        for (int s = 0; s < 32; ++s)
            if ((msk >> s) & 1) { if (cnt == lane) sector = s; cnt++; }
        const bool act = lane < nsec;

        const float* gsec = y_pred + (size_t)b * (size_t)(TT * CC) + sector * 8;
        uint32_t sbase = (uint32_t)__cvta_generic_to_shared(&ring[0]);
        uint32_t dlane = sbase + (uint32_t)lane * 32u;   // compact slot i -> offset i*32B

        // prefill windows 0..PREF-1, one commit group per window
#pragma unroll
        for (int w0 = 0; w0 < PREF; w0++) {
            if (act) {
                const float* s = gsec + (size_t)w0 * WROWS * CC;
                uint32_t d0 = dlane + (uint32_t)(w0 * WROWS * CC) * 4u;
#pragma unroll
                for (int r = 0; r < WROWS; r++) {
                    cpa16(d0 + (uint32_t)(r * CC) * 4u,      s + r * CC);
                    cpa16(d0 + (uint32_t)(r * CC) * 4u + 16, s + r * CC + 4);
                }
            }
            cpcommit();
        }

        // Invariant: 3 groups pending before each wait; wait(2) retires window w.
        // Overwrite of slot (w+PREF)%RING == (w-1)%RING happens after bar_w;
        // the consumer finished reading that slot before arriving at bar_{w-1}.
        for (int w = 0; w < NW; ++w) {
            cpwait2();            // window w landed
            __syncthreads();      // bar_w: release consumer on window w
            if (w + PREF < NW) {
                if (act) {
                    const float* s = gsec + (size_t)(w + PREF) * WROWS * CC;
                    uint32_t d0 = dlane + (uint32_t)(((w + PREF) % RING) * WROWS * CC) * 4u;
#pragma unroll
                    for (int r = 0; r < WROWS; r++) {
                        cpa16(d0 + (uint32_t)(r * CC) * 4u,      s + r * CC);
                        cpa16(d0 + (uint32_t)(r * CC) * 4u + 16, s + r * CC + 4);
                    }
                }
            }
            cpcommit();           // unconditional: uniform group accounting
        }
        return;
    }

    // ============ consumer warp: recursion only ============
    // Class c lives at compacted SMEM offset: cpos(sector(c))*8 + (c&7).
    int   off[SPL];
    float skf[SPL];     // 1 if skip (s-2 -> s) allowed, 0 otherwise
#pragma unroll
    for (int j = 0; j < SPL; j++) {
        int s = lane * SPL + j;
        int c = blank, c2 = blank;
        if (s < SS && (s & 1)) {
            c = lbl[s >> 1];
            if (s >= 3) c2 = lbl[(s >> 1) - 1];
        }
        off[j] = __popc(msk & ((1u << (c >> 3)) - 1u)) * 8 + (c & 7);
        skf[j] = (c != blank && c != c2) ? 1.0f : 0.0f;
    }

    // block-floating-point state: alpha = m * 2^E (per-lane frame)
    float m0 = 0.f, m1 = 0.f, m2 = 0.f, m3 = 0.f, m4 = 0.f;
    int   E  = 0;
    float P[WROWS][SPL];

    // 4 recursion steps + one renorm; sn carries both the frame alignment and
    // the lane-0 boundary (sn=0 kills the out-of-warp neighbor terms).
#define HALF(QS, QE)                                                    \
    {                                                                   \
        int nbE = __shfl_up_sync(FULLM, E, 1);                          \
        if (lane == 0) nbE = E;                                         \
        int d_ = nbE - E;                                               \
        d_ = d_ < -96 ? -96 : (d_ > 96 ? 96 : d_);                      \
        float sn = __int_as_float((d_ + 127) << 23);                    \
        if (lane == 0) sn = 0.0f;                                       \
        _Pragma("unroll")                                               \
        for (int q = (QS); q < (QE); ++q) {                             \
            float nb4 = __shfl_up_sync(FULLM, m4, 1);                   \
            float nb3 = __shfl_up_sync(FULLM, m3, 1);                   \
            float u1 = nb4 * sn;                                        \
            float u2 = nb3 * sn;                                        \
            float n0 = (m0 + u1 + skf[0] * u2) * P[q][0];               \
            float n1 = (m1 + m0 + skf[1] * u1) * P[q][1];               \
            float n2 = (m2 + m1 + skf[2] * m0) * P[q][2];               \
            float n3 = (m3 + m2 + skf[3] * m1) * P[q][3];               \
            float n4 = (m4 + m3 + skf[4] * m2) * P[q][4];               \
            m0 = n0; m1 = n1; m2 = n2; m3 = n3; m4 = n4;                \
        }                                                               \
        float M = fmaxf(fmaxf(fmaxf(m0, m1), fmaxf(m2, m3)), m4);      \
        int eb = __float_as_int(M) >> 23;                               \
        float rs = __int_as_float((254 - eb) << 23);                    \
        m0 *= rs; m1 *= rs; m2 *= rs; m3 *= rs; m4 *= rs;               \
        E = (M > 0.0f) ? (E + eb - 127) : nbE;                          \
    }

    // ---- window 0 (peeled: t=0 consumed by init) ----
    __syncthreads();                      // bar_0
#pragma unroll
    for (int r = 0; r < WROWS; r++)
#pragma unroll
        for (int j = 0; j < SPL; j++)
            P[r][j] = ring[r * CC + off[j]] + EPSF;
    if (lane == 0) { m0 = P[0][0]; m1 = P[0][1]; }   // alpha init at t=0
    HALF(1, 4)
    HALF(4, 8)

    // ---- windows 1..NW-1 ----
    for (int w = 1; w < NW; ++w) {
        __syncthreads();                  // bar_w: window w ready
        const float* rb = &ring[(w & (RING - 1)) * WROWS * CC];
#pragma unroll
        for (int r = 0; r < WROWS; r++)
#pragma unroll
            for (int j = 0; j < SPL; j++)
                P[r][j] = rb[r * CC + off[j]] + EPSF;
        HALF(0, 4)
        HALF(4, 8)
    }
#undef HALF

    // loss = -ln(alpha[S-2] + alpha[S-1]); S-1=128 -> lane25 m3, S-2=127 -> m2
    float tot = m2 + m3;                                  // frame 2^E
    float lf  = (float)E + log2f(fmaxf(tot, 1e-45f));
    float v   = __shfl_sync(FULLM, lf, (SS - 1) / SPL);
    if (lane == 0) out[b] = -LN2F * v;
}

extern "C" void kernel_launch(void* const* d_in, const int* in_sizes, int n_in,
                              void* d_out, int out_size)
{
    const int*   y_true = (const int*)d_in[0];
    const float* y_pred = (const float*)d_in[1];
    // defensive: swap by size if metadata order differs
    if (n_in >= 2 && in_sizes[0] > in_sizes[1]) {
        y_pred = (const float*)d_in[0];
        y_true = (const int*)d_in[1];
    }
    (void)out_size;
    ctc_warp_kernel<<<BB, 64>>>(y_true, y_pred, (float*)d_out);
}

// round 11
// speedup vs baseline: 1.0991x; 1.0991x over previous
#include <cuda_runtime.h>
#include <cstdint>

#define BB 512
#define TT 1024
#define CC 256
#define LL 64
#define SS 129          // 2*LL+1
#define SPL 5           // states per lane (32*5 = 160 >= 129, padded)
#define WROWS 8         // rows per memory window
#define NW (TT / WROWS) // 128 windows
#define RING 6          // ring depth in windows (48 KB SMEM)
#define PREF 5          // prefetch distance (windows)
#define EPSF 1e-7f
#define LN2F 0.69314718055994530942f
#define FULLM 0xffffffffu

__device__ __forceinline__ void cpa16(uint32_t dst, const float* src) {
    asm volatile("cp.async.cg.shared.global [%0], [%1], 16;" :: "r"(dst), "l"(src) : "memory");
}
__device__ __forceinline__ void cpcommit() {
    asm volatile("cp.async.commit_group;" ::: "memory");
}
__device__ __forceinline__ void cpwait4() {
    asm volatile("cp.async.wait_group 4;" ::: "memory");
}

__global__ void __launch_bounds__(64)
ctc_warp_kernel(const int* __restrict__ y_true,
                const float* __restrict__ y_pred,
                float* __restrict__ out)
{
    __shared__ float ring[RING * WROWS * CC];   // 48 KB

    const int b     = blockIdx.x;
    const int tid   = threadIdx.x;
    const int lane  = tid & 31;
    const int wrp   = tid >> 5;
    const int blank = CC - 1;

    if (wrp == 1) {
        // ============ producer warp: owns ALL global->shared traffic ============
        // Each lane covers 8 floats (32 B) of every 256-float row -> TWO 16B cp.async,
        // fully coalesced across lanes (8x 128B lines per row).
        const float* gsrc = y_pred + (size_t)b * (size_t)(TT * CC) + lane * 8;
        uint32_t sl = (uint32_t)__cvta_generic_to_shared(&ring[0]) + lane * 32u;

        // prefill windows 0..PREF-1, one commit group per window
#pragma unroll
        for (int w0 = 0; w0 < PREF; w0++) {
#pragma unroll
            for (int r = 0; r < WROWS; r++) {
                uint32_t dst = sl + (uint32_t)((w0 * WROWS + r) * CC) * 4u;
                cpa16(dst,      gsrc + r * CC);
                cpa16(dst + 16, gsrc + r * CC + 4);
            }
            gsrc += WROWS * CC;
            cpcommit();
        }

        // Invariant: 5 groups pending before each wait; wait(4) retires window w.
        // Overwrite of slot (w+PREF)%RING == (w-1)%RING happens after bar_w; the
        // consumer finished reading slot (w-1)%RING before arriving at bar_{w-1}.
        for (int w = 0; w < NW; ++w) {
            cpwait4();            // window w landed
            __syncthreads();      // bar_w: release consumer on window w
            if (w + PREF < NW) {
                uint32_t dst0 = sl + (uint32_t)(((w + PREF) % RING) * WROWS * CC) * 4u;
#pragma unroll
                for (int r = 0; r < WROWS; r++) {
                    uint32_t dst = dst0 + (uint32_t)(r * CC) * 4u;
                    cpa16(dst,      gsrc + r * CC);
                    cpa16(dst + 16, gsrc + r * CC + 4);
                }
                gsrc += WROWS * CC;
            }
            cpcommit();           // unconditional: uniform group accounting
        }
        return;
    }

    // ============ consumer warp: recursion only ============
    int   cls[SPL];
    float skf[SPL];     // 1 if skip (s-2 -> s) allowed, 0 otherwise
#pragma unroll
    for (int j = 0; j < SPL; j++) {
        int s = lane * SPL + j;
        int c = blank, c2 = blank;
        if (s < SS && (s & 1)) {
            c = y_true[b * LL + (s >> 1)];
            if (s >= 3) c2 = y_true[b * LL + (s >> 1) - 1];
        }
        cls[j] = c;
        skf[j] = (c != blank && c != c2) ? 1.0f : 0.0f;
    }

    // block-floating-point state: alpha = m * 2^E (per-lane frame)
    float m0 = 0.f, m1 = 0.f, m2 = 0.f, m3 = 0.f, m4 = 0.f;
    int   E  = 0;
    float P[WROWS][SPL];

    // 4 recursion steps + one renorm; sn carries both the frame alignment and
    // the lane-0 boundary (sn=0 kills the out-of-warp neighbor terms).
#define HALF(QS, QE)                                                    \
    {                                                                   \
        int nbE = __shfl_up_sync(FULLM, E, 1);                          \
        if (lane == 0) nbE = E;                                         \
        int d_ = nbE - E;                                               \
        d_ = d_ < -96 ? -96 : (d_ > 96 ? 96 : d_);                      \
        float sn = __int_as_float((d_ + 127) << 23);                    \
        if (lane == 0) sn = 0.0f;                                       \
        _Pragma("unroll")                                               \
        for (int q = (QS); q < (QE); ++q) {                             \
            float nb4 = __shfl_up_sync(FULLM, m4, 1);                   \
            float nb3 = __shfl_up_sync(FULLM, m3, 1);                   \
            float u1 = nb4 * sn;                                        \
            float u2 = nb3 * sn;                                        \
            float n0 = (m0 + u1 + skf[0] * u2) * P[q][0];               \
            float n1 = (m1 + m0 + skf[1] * u1) * P[q][1];               \
            float n2 = (m2 + m1 + skf[2] * m0) * P[q][2];               \
            float n3 = (m3 + m2 + skf[3] * m1) * P[q][3];               \
            float n4 = (m4 + m3 + skf[4] * m2) * P[q][4];               \
            m0 = n0; m1 = n1; m2 = n2; m3 = n3; m4 = n4;                \
        }                                                               \
        float M = fmaxf(fmaxf(fmaxf(m0, m1), fmaxf(m2, m3)), m4);      \
        int eb = __float_as_int(M) >> 23;                               \
        float rs = __int_as_float((254 - eb) << 23);                    \
        m0 *= rs; m1 *= rs; m2 *= rs; m3 *= rs; m4 *= rs;               \
        E = (M > 0.0f) ? (E + eb - 127) : nbE;                          \
    }

    // ---- window 0 (peeled: t=0 consumed by init) ----
    __syncthreads();                      // bar_0
#pragma unroll
    for (int r = 0; r < WROWS; r++)
#pragma unroll
        for (int j = 0; j < SPL; j++)
            P[r][j] = ring[r * CC + cls[j]] + EPSF;
    if (lane == 0) { m0 = P[0][0]; m1 = P[0][1]; }   // alpha init at t=0
    HALF(1, 4)
    HALF(4, 8)

    // ---- windows 1..NW-1 ----
    for (int w = 1; w < NW; ++w) {
        __syncthreads();                  // bar_w: window w ready
        const float* rb = &ring[(w % RING) * WROWS * CC];
#pragma unroll
        for (int r = 0; r < WROWS; r++)
#pragma unroll
            for (int j = 0; j < SPL; j++)
                P[r][j] = rb[r * CC + cls[j]] + EPSF;
        HALF(0, 4)
        HALF(4, 8)
    }
#undef HALF

    // loss = -ln(alpha[S-2] + alpha[S-1]); S-1=128 -> lane25 m3, S-2=127 -> m2
    float tot = m2 + m3;                                  // frame 2^E
    float lf  = (float)E + log2f(fmaxf(tot, 1e-45f));
    float v   = __shfl_sync(FULLM, lf, (SS - 1) / SPL);
    if (lane == 0) out[b] = -LN2F * v;
}

extern "C" void kernel_launch(void* const* d_in, const int* in_sizes, int n_in,
                              void* d_out, int out_size)
{
    const int*   y_true = (const int*)d_in[0];
    const float* y_pred = (const float*)d_in[1];
    // defensive: swap by size if metadata order differs
    if (n_in >= 2 && in_sizes[0] > in_sizes[1]) {
        y_pred = (const float*)d_in[0];
        y_true = (const int*)d_in[1];
    }
    (void)out_size;
    ctc_warp_kernel<<<BB, 64>>>(y_true, y_pred, (float*)d_out);
}

// round 12
// speedup vs baseline: 1.1488x; 1.0452x over previous
#include <cuda_runtime.h>
#include <cstdint>

#define BB 512
#define TT 1024
#define CC 256
#define LL 64
#define SS 129          // 2*LL+1
#define SPL 5           // states per lane (32*5 = 160 >= 129, padded)
#define WROWS 8         // rows per memory window
#define NW (TT / WROWS) // 128 windows
#define RING 4          // ring depth in windows (32 KB SMEM)
#define PREF 3          // prefetch distance (windows)
#define EPSF 1e-7f
#define LN2F 0.69314718055994530942f
#define FULLM 0xffffffffu

__device__ __forceinline__ void cpa16(uint32_t dst, const float* src) {
    asm volatile("cp.async.cg.shared.global [%0], [%1], 16;" :: "r"(dst), "l"(src) : "memory");
}
__device__ __forceinline__ void cpcommit() {
    asm volatile("cp.async.commit_group;" ::: "memory");
}
__device__ __forceinline__ void cpwait2() {
    asm volatile("cp.async.wait_group 2;" ::: "memory");
}
// split named barriers: id1 = "window ready" (prod->cons), id2 = "gather done" (cons->prod)
__device__ __forceinline__ void bar_arrive_ready() { asm volatile("bar.arrive 1, 64;" ::: "memory"); }
__device__ __forceinline__ void bar_sync_ready()   { asm volatile("bar.sync   1, 64;" ::: "memory"); }
__device__ __forceinline__ void bar_arrive_done()  { asm volatile("bar.arrive 2, 64;" ::: "memory"); }
__device__ __forceinline__ void bar_sync_done()    { asm volatile("bar.sync   2, 64;" ::: "memory"); }

__global__ void __launch_bounds__(64)
ctc_warp_kernel(const int* __restrict__ y_true,
                const float* __restrict__ y_pred,
                float* __restrict__ out)
{
    __shared__ float ring[RING * WROWS * CC];   // 32 KB

    const int b     = blockIdx.x;
    const int tid   = threadIdx.x;
    const int lane  = tid & 31;
    const int wrp   = tid >> 5;
    const int blank = CC - 1;

    if (wrp == 1) {
        // ============ producer warp: owns ALL global->shared traffic ============
        const float* gsrc = y_pred + (size_t)b * (size_t)(TT * CC) + lane * 8;
        uint32_t sl = (uint32_t)__cvta_generic_to_shared(&ring[0]) + lane * 32u;

        // prefill windows 0..PREF-1 (slots 0..2), one commit group per window
#pragma unroll
        for (int w0 = 0; w0 < PREF; w0++) {
#pragma unroll
            for (int r = 0; r < WROWS; r++) {
                uint32_t dst = sl + (uint32_t)((w0 * WROWS + r) * CC) * 4u;
                cpa16(dst,      gsrc + r * CC);
                cpa16(dst + 16, gsrc + r * CC + 4);
            }
            gsrc += WROWS * CC;
            cpcommit();
        }

        // Phase-safe schedule: sync(done_{w-1}) BEFORE arrive(ready_w) keeps both
        // barriers strictly 1:1 (no arriver ever 2 phases ahead).
        for (int w = 0; w < NW; ++w) {
            cpwait2();                    // window w landed (3 pending -> 2)
            if (w >= 1) bar_sync_done();  // consumer finished gather w-1
            bar_arrive_ready();           // publish window w
            if (w + PREF < NW) {          // overwrite slot last gathered at w-1
                uint32_t dst0 = sl + (uint32_t)(((w + PREF) % RING) * WROWS * CC) * 4u;
#pragma unroll
                for (int r = 0; r < WROWS; r++) {
                    uint32_t dst = dst0 + (uint32_t)(r * CC) * 4u;
                    cpa16(dst,      gsrc + r * CC);
                    cpa16(dst + 16, gsrc + r * CC + 4);
                }
                gsrc += WROWS * CC;
            }
            cpcommit();                   // unconditional: uniform group accounting
        }
        return;
    }

    // ============ consumer warp: recursion only ============
    int   cls[SPL];
    float skf[SPL];     // 1 if skip (s-2 -> s) allowed, 0 otherwise
#pragma unroll
    for (int j = 0; j < SPL; j++) {
        int s = lane * SPL + j;
        int c = blank, c2 = blank;
        if (s < SS && (s & 1)) {
            c = y_true[b * LL + (s >> 1)];
            if (s >= 3) c2 = y_true[b * LL + (s >> 1) - 1];
        }
        cls[j] = c;
        skf[j] = (c != blank && c != c2) ? 1.0f : 0.0f;
    }

    // block-floating-point state: alpha = m * 2^E (per-lane frame)
    float m0 = 0.f, m1 = 0.f, m2 = 0.f, m3 = 0.f, m4 = 0.f;
    int   E  = 0;
    float P[WROWS][SPL];

#define HALF(QS, QE)                                                    \
    {                                                                   \
        int nbE = __shfl_up_sync(FULLM, E, 1);                          \
        if (lane == 0) nbE = E;                                         \
        int d_ = nbE - E;                                               \
        d_ = d_ < -96 ? -96 : (d_ > 96 ? 96 : d_);                      \
        float sn = __int_as_float((d_ + 127) << 23);                    \
        if (lane == 0) sn = 0.0f;                                       \
        _Pragma("unroll")                                               \
        for (int q = (QS); q < (QE); ++q) {                             \
            float nb4 = __shfl_up_sync(FULLM, m4, 1);                   \
            float nb3 = __shfl_up_sync(FULLM, m3, 1);                   \
            float u1 = nb4 * sn;                                        \
            float u2 = nb3 * sn;                                        \
            float n0 = (m0 + u1 + skf[0] * u2) * P[q][0];               \
            float n1 = (m1 + m0 + skf[1] * u1) * P[q][1];               \
            float n2 = (m2 + m1 + skf[2] * m0) * P[q][2];               \
            float n3 = (m3 + m2 + skf[3] * m1) * P[q][3];               \
            float n4 = (m4 + m3 + skf[4] * m2) * P[q][4];               \
            m0 = n0; m1 = n1; m2 = n2; m3 = n3; m4 = n4;                \
        }                                                               \
        float M = fmaxf(fmaxf(fmaxf(m0, m1), fmaxf(m2, m3)), m4);      \
        int eb = __float_as_int(M) >> 23;                               \
        float rs = __int_as_float((254 - eb) << 23);                    \
        m0 *= rs; m1 *= rs; m2 *= rs; m3 *= rs; m4 *= rs;               \
        E = (M > 0.0f) ? (E + eb - 127) : nbE;                          \
    }

    // ---- window 0 (peeled: t=0 consumed by init) ----
    bar_sync_ready();                     // ready_0
#pragma unroll
    for (int r = 0; r < WROWS; r++)
#pragma unroll
        for (int j = 0; j < SPL; j++)
            P[r][j] = ring[r * CC + cls[j]] + EPSF;
    bar_arrive_done();                    // done_0 (slot 0 reusable)
    if (lane == 0) { m0 = P[0][0]; m1 = P[0][1]; }   // alpha init at t=0
    HALF(1, 4)
    HALF(4, 8)

    // ---- windows 1..NW-1 ----
    for (int w = 1; w < NW; ++w) {
        bar_sync_ready();                 // ready_w
        const float* rb = &ring[(w & (RING - 1)) * WROWS * CC];
#pragma unroll
        for (int r = 0; r < WROWS; r++)
#pragma unroll
            for (int j = 0; j < SPL; j++)
                P[r][j] = rb[r * CC + cls[j]] + EPSF;
        if (w < NW - 1) bar_arrive_done();  // done_w (matched: producer syncs NW-1)
        HALF(0, 4)
        HALF(4, 8)
    }
#undef HALF

    // loss = -ln(alpha[S-2] + alpha[S-1]); S-1=128 -> lane25 m3, S-2=127 -> m2
    float tot = m2 + m3;                                  // frame 2^E
    float lf  = (float)E + log2f(fmaxf(tot, 1e-45f));
    float v   = __shfl_sync(FULLM, lf, (SS - 1) / SPL);
    if (lane == 0) out[b] = -LN2F * v;
}

extern "C" void kernel_launch(void* const* d_in, const int* in_sizes, int n_in,
                              void* d_out, int out_size)
{
    const int*   y_true = (const int*)d_in[0];
    const float* y_pred = (const float*)d_in[1];
    // defensive: swap by size if metadata order differs
    if (n_in >= 2 && in_sizes[0] > in_sizes[1]) {
        y_pred = (const float*)d_in[0];
        y_true = (const int*)d_in[1];
    }
    (void)out_size;
    ctc_warp_kernel<<<BB, 64>>>(y_true, y_pred, (float*)d_out);
}